// round 1
// baseline (speedup 1.0000x reference)
#include <cuda_runtime.h>
#include <float.h>
#include <math.h>

#define CCH 128
#define HWF 409600
#define WF 640
#define HF 640

// Precomputed M = W^T W (symmetric) and u = W^T b
__device__ float d_M[CCH * CCH];
__device__ float d_u[CCH];

// Block o computes row o of M and u[o].
__global__ void precompute_Mu(const float* __restrict__ W, const float* __restrict__ b) {
    __shared__ float wcol[CCH];
    int o = blockIdx.x, t = threadIdx.x;
    wcol[t] = W[t * CCH + o];
    __syncthreads();
    float acc = 0.f;
#pragma unroll 8
    for (int k = 0; k < CCH; k++) acc += wcol[k] * W[k * CCH + t];
    d_M[o * CCH + t] = acc;
    if (t == 0) {
        float uu = 0.f;
        for (int k = 0; k < CCH; k++) uu += wcol[k] * b[k];
        d_u[o] = uu;
    }
}

// Dynamic smem layout (floats):
// [0, 16384)        Msh  (M, symmetric so row/col indexing interchangeable)
// [16384, 16512)    ush
// [16512, 17536)    r0p  : r0p[c*8 + q], q = point-in-batch (8 points)
// [17536, 18560)    gsh  : gsh[q*128 + o]
// [18560, 18576)    hf   : b1x[8], b1y[8]
// ints at +18576    hi   : off0[8], pix1base[8], valid[8]
#define SM_FLOATS 18624

__global__ void __launch_bounds__(256, 3)
refine_kernel(const float* __restrict__ mk0, const float* __restrict__ mk1,
              const float* __restrict__ f0, const float* __restrict__ f1,
              const int* __restrict__ stride_ptr,
              float* __restrict__ out, int N, int ptsPerBlock)
{
    extern __shared__ float sm[];
    float* Msh = sm;
    float* ush = sm + 16384;
    float* r0p = sm + 16512;
    float* gsh = sm + 17536;
    float* hf  = sm + 18560;
    int*   hi  = (int*)(sm + 18576);

    const int t = threadIdx.x;
    const int stride = stride_ptr ? __ldg(stride_ptr) : 8;
    const int fr = stride >> 1;                 // fine_ratio = stride // 2
    const float scalef = (float)(stride / fr);  // scale = stride // fine_ratio
    const float halfstr = (float)(stride >> 1); // stride // 2

    // Stage M and u in shared.
    for (int i = t; i < CCH * CCH; i += 256) Msh[i] = d_M[i];
    if (t < CCH) ush[t] = d_u[t];

    const int o    = t & 127;
    const int half = t >> 7;     // 0 or 1: which 4-point group this thread serves
    const int wid  = t >> 5;     // warp id 0..7: point handled in phase 2
    const int lane = t & 31;

    const int n0blk = blockIdx.x * ptsPerBlock;

    for (int nb = 0; nb < ptsPerBlock; nb += 8) {
        const int n0 = n0blk + nb;
        if (n0 >= N) break;

        __syncthreads();  // previous batch fully consumed smem

        // ---- header: threads 0..7, one point each ----
        if (t < 8) {
            int n = n0 + t;
            int nc = n < N ? n : N - 1;
            float m0x = mk0[2 * nc], m0y = mk0[2 * nc + 1];
            float m1x = mk1[2 * nc], m1y = mk1[2 * nc + 1];
            int cx0 = (int)(m0x * (float)fr), cy0 = (int)(m0y * (float)fr);
            int cx1 = (int)(m1x * (float)fr), cy1 = (int)(m1y * (float)fr);
            int v = (cx0 >= 2 && cx0 + 2 < WF && cy0 >= 2 && cy0 + 2 < HF &&
                     cx1 >= 2 && cx1 + 2 < WF && cy1 >= 2 && cy1 + 2 < HF);
            int cx0c = min(max(cx0, 2), WF - 3), cy0c = min(max(cy0, 2), HF - 3);
            int cx1c = min(max(cx1, 2), WF - 3), cy1c = min(max(cy1, 2), HF - 3);
            hi[t]      = cy0c * WF + cx0c;   // center offset in f0
            hi[8 + t]  = cy1c * WF + cx1c;   // patch-center offset in f1
            hi[16 + t] = v;
            hf[t]      = m1x * (float)stride + halfstr;  // pts1 base x
            hf[8 + t]  = m1y * (float)stride + halfstr;  // pts1 base y
            if (n < N) {
                out[2 * n]     = m0x * (float)stride + halfstr;  // pts0
                out[2 * n + 1] = m0y * (float)stride + halfstr;
            }
        }
        __syncthreads();

        // ---- r0 gather: thread (o, half) loads 4 centers for its 4 points ----
        {
            const float* fp = f0 + (size_t)o * HWF;
            int b0 = hi[half * 4 + 0];
            int b1 = hi[half * 4 + 1];
            int b2 = hi[half * 4 + 2];
            int b3 = hi[half * 4 + 3];
            float v0 = __ldg(fp + b0);
            float v1 = __ldg(fp + b1);
            float v2 = __ldg(fp + b2);
            float v3 = __ldg(fp + b3);
            float4* dst = (float4*)&r0p[o * 8 + half * 4];
            *dst = make_float4(v0, v1, v2, v3);
        }
        __syncthreads();

        // ---- phase 1: g[q] = M * r0[q] + u  (each half-block: 4 points) ----
        {
            float a0 = ush[o], a1 = a0, a2 = a0, a3 = a0;
#pragma unroll 4
            for (int c = 0; c < CCH; c++) {
                float m = Msh[c * CCH + o];           // symmetric: M[c][o]==M[o][c]
                float4 rv = *(const float4*)&r0p[c * 8 + half * 4];  // broadcast
                a0 += m * rv.x; a1 += m * rv.y; a2 += m * rv.z; a3 += m * rv.w;
            }
            int qb = half * 4;
            gsh[(qb + 0) * CCH + o] = a0;
            gsh[(qb + 1) * CCH + o] = a1;
            gsh[(qb + 2) * CCH + o] = a2;
            gsh[(qb + 3) * CCH + o] = a3;
        }
        __syncthreads();

        // ---- phase 2: warp `wid` handles point wid; lanes 0..24 = patch pixels ----
        {
            const int n = n0 + wid;
            const int p = lane;
            const bool inpatch = p < 25;
            const int pixb = hi[8 + wid];
            const int dy = p / 5 - 2;
            const int dx = p % 5 - 2;
            const int pix = inpatch ? (pixb + dy * WF + dx) : pixb;
            const float* p1 = f1 + pix;
            const float* gq = &gsh[wid * CCH];

            float corr = 0.f;
#pragma unroll 4
            for (int c = 0; c < CCH; c += 8) {
                float v0 = __ldg(p1 + (size_t)(c + 0) * HWF);
                float v1 = __ldg(p1 + (size_t)(c + 1) * HWF);
                float v2 = __ldg(p1 + (size_t)(c + 2) * HWF);
                float v3 = __ldg(p1 + (size_t)(c + 3) * HWF);
                float v4 = __ldg(p1 + (size_t)(c + 4) * HWF);
                float v5 = __ldg(p1 + (size_t)(c + 5) * HWF);
                float v6 = __ldg(p1 + (size_t)(c + 6) * HWF);
                float v7 = __ldg(p1 + (size_t)(c + 7) * HWF);
                float4 g0 = *(const float4*)&gq[c];
                float4 g1 = *(const float4*)&gq[c + 4];
                corr += g0.x * v0 + g0.y * v1 + g0.z * v2 + g0.w * v3
                      + g1.x * v4 + g1.y * v5 + g1.z * v6 + g1.w * v7;
            }

            // softmax over the 25 lanes (the per-point constant term cancels here)
            float cm = inpatch ? corr : -FLT_MAX;
#pragma unroll
            for (int d = 16; d; d >>= 1)
                cm = fmaxf(cm, __shfl_xor_sync(0xffffffffu, cm, d));
            float e  = inpatch ? __expf(corr - cm) : 0.f;
            float ex = e * (float)dx;
            float ey = e * (float)dy;
            float s  = e;
#pragma unroll
            for (int d = 16; d; d >>= 1) {
                s  += __shfl_xor_sync(0xffffffffu, s,  d);
                ex += __shfl_xor_sync(0xffffffffu, ex, d);
                ey += __shfl_xor_sync(0xffffffffu, ey, d);
            }
            if (lane == 0 && n < N) {
                float inv = scalef / s;
                int v = hi[16 + wid];
                float ox = v ? ex * inv : 0.f;
                float oy = v ? ey * inv : 0.f;
                out[2 * N + 2 * n]     = hf[wid]     + ox;
                out[2 * N + 2 * n + 1] = hf[8 + wid] + oy;
            }
        }
    }
}

extern "C" void kernel_launch(void* const* d_in, const int* in_sizes, int n_in,
                              void* d_out, int out_size) {
    const float* mk0 = (const float*)d_in[0];
    const float* mk1 = (const float*)d_in[1];
    const float* f0  = (const float*)d_in[2];
    const float* f1  = (const float*)d_in[3];
    const float* pw  = (const float*)d_in[4];
    const float* pb  = (const float*)d_in[5];
    const int* stridep = (n_in >= 7) ? (const int*)d_in[6] : nullptr;
    float* out = (float*)d_out;

    int N = in_sizes[0] / 2;

    precompute_Mu<<<128, 128>>>(pw, pb);

    int smbytes = SM_FLOATS * 4;
    cudaFuncSetAttribute(refine_kernel,
                         cudaFuncAttributeMaxDynamicSharedMemorySize, smbytes);
    int ppb = 40;
    int grid = (N + ppb - 1) / ppb;
    refine_kernel<<<grid, 256, smbytes>>>(mk0, mk1, f0, f1, stridep, out, N, ppb);
}

// round 2
// speedup vs baseline: 2.0268x; 2.0268x over previous
#include <cuda_runtime.h>
#include <float.h>
#include <math.h>

#define CCH 128
#define HWF 409600   // 640*640
#define WF 640
#define HF 640

// Precomputed M = W^T W (symmetric) and u = W^T b
__device__ float d_M[CCH * CCH];
__device__ float d_u[CCH];
// Transposed f1: [H*W][C] (pixel-major, channels contiguous)
__device__ float d_f1t[(size_t)HWF * CCH];
// Per-point projected center feature g[n] = M * r0[n] + u
__device__ float d_g[20000 * CCH];

// ---------------------------------------------------------------------------
// Kernel 1: M = W^T W, u = W^T b. Block o computes row o.
__global__ void precompute_Mu(const float* __restrict__ W, const float* __restrict__ b) {
    __shared__ float wcol[CCH];
    int o = blockIdx.x, t = threadIdx.x;
    wcol[t] = W[t * CCH + o];
    __syncthreads();
    float acc = 0.f;
#pragma unroll 8
    for (int k = 0; k < CCH; k++) acc += wcol[k] * W[k * CCH + t];
    d_M[o * CCH + t] = acc;
    if (t == 0) {
        float uu = 0.f;
        for (int k = 0; k < CCH; k++) uu += wcol[k] * b[k];
        d_u[o] = uu;
    }
}

// ---------------------------------------------------------------------------
// Kernel 2: transpose f1 (C,HW) -> d_f1t (HW,C). 64 pixels per block.
#define TP_PIX 64
__global__ void __launch_bounds__(256) transpose_f1(const float* __restrict__ f1) {
    __shared__ float tile[CCH][TP_PIX + 1];   // 128 x 65 floats = 33,280 B
    const int t = threadIdx.x;
    const int pb = blockIdx.x * TP_PIX;
#pragma unroll 8
    for (int i = 0; i < 32; i++) {
        int idx = i * 256 + t;
        int c  = idx >> 6;      // 0..127
        int tx = idx & 63;      // 0..63
        tile[c][tx] = __ldg(f1 + (size_t)c * HWF + pb + tx);
    }
    __syncthreads();
    const int lane = t & 31;
    const int wid  = t >> 5;
#pragma unroll
    for (int pass = 0; pass < 8; pass++) {
        int p = pass * 8 + wid;
        size_t base = (size_t)(pb + p) * CCH;
#pragma unroll
        for (int j = 0; j < 4; j++)
            d_f1t[base + j * 32 + lane] = tile[j * 32 + lane][p];
    }
}

// ---------------------------------------------------------------------------
// Kernel 3: g[n] = M * r0[n] + u. Batches of 8 points, M staged in smem.
// smem floats: Msh[16384] ush[128] r0p[1024] hi[8 ints]
#define G_SM_FLOATS (16384 + 128 + 1024 + 16)
__global__ void __launch_bounds__(256, 3)
g_kernel(const float* __restrict__ mk0, const float* __restrict__ f0,
         const int* __restrict__ stride_ptr, int N, int ptsPerBlock)
{
    extern __shared__ float sm[];
    float* Msh = sm;
    float* ush = sm + 16384;
    float* r0p = sm + 16512;
    int*   hi  = (int*)(sm + 17536);

    const int t = threadIdx.x;
    const int stride = stride_ptr ? __ldg(stride_ptr) : 8;
    const int fr = stride >> 1;

    for (int i = t; i < CCH * CCH; i += 256) Msh[i] = d_M[i];
    if (t < CCH) ush[t] = d_u[t];

    const int o    = t & 127;
    const int half = t >> 7;
    const int n0blk = blockIdx.x * ptsPerBlock;

    for (int nb = 0; nb < ptsPerBlock; nb += 8) {
        const int n0 = n0blk + nb;
        if (n0 >= N) break;
        __syncthreads();

        if (t < 8) {
            int n = n0 + t;
            int nc = n < N ? n : N - 1;
            float m0x = mk0[2 * nc], m0y = mk0[2 * nc + 1];
            int cx0 = (int)(m0x * (float)fr), cy0 = (int)(m0y * (float)fr);
            int cx0c = min(max(cx0, 2), WF - 3), cy0c = min(max(cy0, 2), HF - 3);
            hi[t] = cy0c * WF + cx0c;
        }
        __syncthreads();

        {   // gather 4 center features per thread
            const float* fp = f0 + (size_t)o * HWF;
            int b0 = hi[half * 4 + 0], b1 = hi[half * 4 + 1];
            int b2 = hi[half * 4 + 2], b3 = hi[half * 4 + 3];
            float v0 = __ldg(fp + b0), v1 = __ldg(fp + b1);
            float v2 = __ldg(fp + b2), v3 = __ldg(fp + b3);
            *(float4*)&r0p[o * 8 + half * 4] = make_float4(v0, v1, v2, v3);
        }
        __syncthreads();

        {   // matvec: 4 points per half-block
            float a0 = ush[o], a1 = a0, a2 = a0, a3 = a0;
#pragma unroll 4
            for (int c = 0; c < CCH; c++) {
                float m = Msh[c * CCH + o];
                float4 rv = *(const float4*)&r0p[c * 8 + half * 4];
                a0 += m * rv.x; a1 += m * rv.y; a2 += m * rv.z; a3 += m * rv.w;
            }
            int qb = half * 4;
            if (n0 + qb + 0 < N) d_g[(size_t)(n0 + qb + 0) * CCH + o] = a0;
            if (n0 + qb + 1 < N) d_g[(size_t)(n0 + qb + 1) * CCH + o] = a1;
            if (n0 + qb + 2 < N) d_g[(size_t)(n0 + qb + 2) * CCH + o] = a2;
            if (n0 + qb + 3 < N) d_g[(size_t)(n0 + qb + 3) * CCH + o] = a3;
        }
    }
}

// ---------------------------------------------------------------------------
// Kernel 4: one warp per point: correlation + softmax + outputs.
__device__ __forceinline__ float wred(float v) {
#pragma unroll
    for (int d = 16; d; d >>= 1) v += __shfl_xor_sync(0xffffffffu, v, d);
    return v;
}

__global__ void __launch_bounds__(256)
corr_kernel(const float* __restrict__ mk0, const float* __restrict__ mk1,
            const int* __restrict__ stride_ptr, float* __restrict__ out, int N)
{
    const int wid = threadIdx.x >> 5, lane = threadIdx.x & 31;
    const int n = blockIdx.x * 8 + wid;
    if (n >= N) return;

    const int stride = stride_ptr ? __ldg(stride_ptr) : 8;
    const int fr = stride >> 1;
    const float scalef = (float)(stride / fr);
    const float halfstr = (float)(stride >> 1);

    const float m0x = __ldg(&mk0[2 * n]), m0y = __ldg(&mk0[2 * n + 1]);
    const float m1x = __ldg(&mk1[2 * n]), m1y = __ldg(&mk1[2 * n + 1]);
    const int cx0 = (int)(m0x * (float)fr), cy0 = (int)(m0y * (float)fr);
    const int cx1 = (int)(m1x * (float)fr), cy1 = (int)(m1y * (float)fr);
    const bool valid = cx0 >= 2 && cx0 + 2 < WF && cy0 >= 2 && cy0 + 2 < HF &&
                       cx1 >= 2 && cx1 + 2 < WF && cy1 >= 2 && cy1 + 2 < HF;
    const int cx1c = min(max(cx1, 2), WF - 3);
    const int cy1c = min(max(cy1, 2), HF - 3);
    const size_t pixb = (size_t)cy1c * WF + cx1c;

    const float4 g4 = *(const float4*)&d_g[(size_t)n * CCH + lane * 4];

    float corr = -FLT_MAX;   // lane p (p<25) ends up holding corr[p]
#pragma unroll
    for (int row = 0; row < 5; row++) {
        const size_t rb = (pixb + (size_t)(row - 2) * WF - 2) * CCH + lane * 4;
        float4 v0 = __ldg((const float4*)&d_f1t[rb]);
        float4 v1 = __ldg((const float4*)&d_f1t[rb + CCH]);
        float4 v2 = __ldg((const float4*)&d_f1t[rb + 2 * CCH]);
        float4 v3 = __ldg((const float4*)&d_f1t[rb + 3 * CCH]);
        float4 v4 = __ldg((const float4*)&d_f1t[rb + 4 * CCH]);
        float r0 = g4.x * v0.x + g4.y * v0.y + g4.z * v0.z + g4.w * v0.w;
        float r1 = g4.x * v1.x + g4.y * v1.y + g4.z * v1.z + g4.w * v1.w;
        float r2 = g4.x * v2.x + g4.y * v2.y + g4.z * v2.z + g4.w * v2.w;
        float r3 = g4.x * v3.x + g4.y * v3.y + g4.z * v3.z + g4.w * v3.w;
        float r4 = g4.x * v4.x + g4.y * v4.y + g4.z * v4.z + g4.w * v4.w;
#pragma unroll
        for (int d = 16; d; d >>= 1) {
            r0 += __shfl_xor_sync(0xffffffffu, r0, d);
            r1 += __shfl_xor_sync(0xffffffffu, r1, d);
            r2 += __shfl_xor_sync(0xffffffffu, r2, d);
            r3 += __shfl_xor_sync(0xffffffffu, r3, d);
            r4 += __shfl_xor_sync(0xffffffffu, r4, d);
        }
        const int p0 = row * 5;
        if (lane == p0 + 0) corr = r0;
        if (lane == p0 + 1) corr = r1;
        if (lane == p0 + 2) corr = r2;
        if (lane == p0 + 3) corr = r3;
        if (lane == p0 + 4) corr = r4;
    }

    // softmax over lanes 0..24 + expectation (constant term cancels)
    const bool inpatch = lane < 25;
    const int dx = lane % 5 - 2;
    const int dy = lane / 5 - 2;
    float cm = corr;
#pragma unroll
    for (int d = 16; d; d >>= 1)
        cm = fmaxf(cm, __shfl_xor_sync(0xffffffffu, cm, d));
    float e  = inpatch ? __expf(corr - cm) : 0.f;
    float ex = e * (float)dx;
    float ey = e * (float)dy;
    float s  = e;
#pragma unroll
    for (int d = 16; d; d >>= 1) {
        s  += __shfl_xor_sync(0xffffffffu, s,  d);
        ex += __shfl_xor_sync(0xffffffffu, ex, d);
        ey += __shfl_xor_sync(0xffffffffu, ey, d);
    }
    if (lane == 0) {
        out[2 * n]     = m0x * (float)stride + halfstr;
        out[2 * n + 1] = m0y * (float)stride + halfstr;
        const float inv = scalef / s;
        const float ox = valid ? ex * inv : 0.f;
        const float oy = valid ? ey * inv : 0.f;
        out[2 * N + 2 * n]     = m1x * (float)stride + halfstr + ox;
        out[2 * N + 2 * n + 1] = m1y * (float)stride + halfstr + oy;
    }
}

// ---------------------------------------------------------------------------
extern "C" void kernel_launch(void* const* d_in, const int* in_sizes, int n_in,
                              void* d_out, int out_size) {
    const float* mk0 = (const float*)d_in[0];
    const float* mk1 = (const float*)d_in[1];
    const float* f0  = (const float*)d_in[2];
    const float* f1  = (const float*)d_in[3];
    const float* pw  = (const float*)d_in[4];
    const float* pb  = (const float*)d_in[5];
    const int* stridep = (n_in >= 7) ? (const int*)d_in[6] : nullptr;
    float* out = (float*)d_out;

    int N = in_sizes[0] / 2;

    precompute_Mu<<<128, 128>>>(pw, pb);
    transpose_f1<<<HWF / TP_PIX, 256>>>(f1);

    int smbytes = G_SM_FLOATS * 4;
    cudaFuncSetAttribute(g_kernel,
                         cudaFuncAttributeMaxDynamicSharedMemorySize, smbytes);
    int ppb = 40;
    int grid = (N + ppb - 1) / ppb;
    g_kernel<<<grid, 256, smbytes>>>(mk0, f0, stridep, N, ppb);

    corr_kernel<<<(N + 7) / 8, 256>>>(mk0, mk1, stridep, out, N);
}

// round 5
// speedup vs baseline: 2.7441x; 1.3539x over previous
#include <cuda_runtime.h>
#include <cuda_fp16.h>
#include <float.h>
#include <math.h>

#define CCH 128
#define HWF 409600   // 640*640
#define WF 640
#define HF 640

// Precomputed M = W^T W (symmetric) and u = W^T b
__device__ float d_M[CCH * CCH];
__device__ float d_u[CCH];
// Transposed f1 in fp16: [H*W][128 slots]; slot s holds channel c(s) = (s&3)*32 + (s>>2)
__device__ __half d_f1t[(size_t)HWF * CCH];
// g[n] = M * r0[n] + u, stored slot-permuted to match d_f1t
__device__ float d_g[20000 * CCH];

// packed fp32x2 FMA (Blackwell): d = a*b + c elementwise on 2 packed floats
#define FMA_F32X2(d, a, b, c) \
    asm("fma.rn.f32x2 %0, %1, %2, %3;" : "=l"(d) : "l"(a), "l"(b), "l"(c))

__device__ __forceinline__ unsigned long long pack_f32x2(float lo, float hi) {
    unsigned long long r;
    unsigned ulo = __float_as_uint(lo), uhi = __float_as_uint(hi);
    asm("mov.b64 %0, {%1, %2};" : "=l"(r) : "r"(ulo), "r"(uhi));
    return r;
}
__device__ __forceinline__ void unpack_f32x2(unsigned long long v, float& lo, float& hi) {
    unsigned ulo, uhi;
    asm("mov.b64 {%0, %1}, %2;" : "=r"(ulo), "=r"(uhi) : "l"(v));
    lo = __uint_as_float(ulo);
    hi = __uint_as_float(uhi);
}

// ---------------------------------------------------------------------------
// Kernel 1: M = W^T W, u = W^T b. Block o computes row o.
__global__ void precompute_Mu(const float* __restrict__ W, const float* __restrict__ b) {
    __shared__ float wcol[CCH];
    int o = blockIdx.x, t = threadIdx.x;
    wcol[t] = W[t * CCH + o];
    __syncthreads();
    float acc = 0.f;
#pragma unroll 8
    for (int k = 0; k < CCH; k++) acc += wcol[k] * W[k * CCH + t];
    d_M[o * CCH + t] = acc;
    if (t == 0) {
        float uu = 0.f;
        for (int k = 0; k < CCH; k++) uu += wcol[k] * b[k];
        d_u[o] = uu;
    }
}

// ---------------------------------------------------------------------------
// Kernel 2: transpose+convert f1 (C,HW) fp32 -> d_f1t (HW, slots) fp16.
// 64 pixels/block. smem tile fp32 [128 ch][pitch 65] -> column reads conflict-free.
#define TP_PIX 64
__global__ void __launch_bounds__(256) transpose_f1(const float* __restrict__ f1) {
    __shared__ float tile[CCH * 65];
    const int t = threadIdx.x;
    const int pb = blockIdx.x * TP_PIX;
    const int lane = t & 31, wid = t >> 5;

    // Load: 2048 float4 from gmem (coalesced). Scalar STS into pitch-65 tile
    // (float4 STS would be misaligned for odd channels; scalar is safe, ~2-way).
#pragma unroll
    for (int it = 0; it < 8; it++) {
        int idx = it * 256 + t;
        int c = idx >> 4;        // 0..127
        int g = idx & 15;        // float4 group within the 64-pixel row
        float4 v = __ldg((const float4*)(f1 + (size_t)c * HWF + pb + 4 * g));
        float* dst = &tile[c * 65 + 4 * g];
        dst[0] = v.x; dst[1] = v.y; dst[2] = v.z; dst[3] = v.w;
    }
    __syncthreads();

    // Write: one pixel per warp-pass. Lane l reads rows {l, l+32, l+64, l+96},
    // column p: bank = (l + p) % 32 -> conflict-free. Packs slots 4l..4l+3.
#pragma unroll
    for (int pass = 0; pass < 8; pass++) {
        int p = pass * 8 + wid;
        float v0 = tile[(lane      ) * 65 + p];
        float v1 = tile[(lane + 32 ) * 65 + p];
        float v2 = tile[(lane + 64 ) * 65 + p];
        float v3 = tile[(lane + 96 ) * 65 + p];
        __half2 h0 = __floats2half2_rn(v0, v1);
        __half2 h1 = __floats2half2_rn(v2, v3);
        uint2 u;
        u.x = *reinterpret_cast<unsigned*>(&h0);
        u.y = *reinterpret_cast<unsigned*>(&h1);
        *reinterpret_cast<uint2*>(d_f1t + (size_t)(pb + p) * CCH + lane * 4) = u;
    }
}

// ---------------------------------------------------------------------------
// Kernel 3: g[n] = M * r0[n] + u, 16 points per batch, FFMA2 matvec.
// smem floats: Msh[16384] ush[128] r0p[128*20] hi[16 ints]
#define R0PITCH 20   // 80 B rows: 16B-aligned at every half*8 offset
#define G_SM_FLOATS (16384 + 128 + CCH * R0PITCH + 16)
__global__ void __launch_bounds__(256, 3)
g_kernel(const float* __restrict__ mk0, const float* __restrict__ f0,
         const int* __restrict__ stride_ptr, int N, int ptsPerBlock)
{
    extern __shared__ float sm[];
    float* Msh = sm;
    float* ush = sm + 16384;
    float* r0p = sm + 16512;
    int*   hi  = (int*)(sm + 16512 + CCH * R0PITCH);

    const int t = threadIdx.x;
    const int stride = stride_ptr ? __ldg(stride_ptr) : 8;
    const int fr = stride >> 1;

    {   // stage M (float4) and u
        const float4* Ms4 = (const float4*)d_M;
        float4* Md4 = (float4*)Msh;
#pragma unroll
        for (int i = 0; i < 16; i++) Md4[i * 256 + t] = __ldg(&Ms4[i * 256 + t]);
        if (t < CCH) ush[t] = d_u[t];
    }

    const int o    = t & 127;
    const int half = t >> 7;
    const int n0blk = blockIdx.x * ptsPerBlock;

    for (int nb = 0; nb < ptsPerBlock; nb += 16) {
        const int n0 = n0blk + nb;
        if (n0 >= N) break;
        __syncthreads();

        if (t < 16) {
            int n = n0 + t;
            int nc = n < N ? n : N - 1;
            float m0x = mk0[2 * nc], m0y = mk0[2 * nc + 1];
            int cx0 = (int)(m0x * (float)fr), cy0 = (int)(m0y * (float)fr);
            int cx0c = min(max(cx0, 2), WF - 3), cy0c = min(max(cy0, 2), HF - 3);
            hi[t] = cy0c * WF + cx0c;
        }
        __syncthreads();

        {   // gather 8 center values per thread (its half's 8 points, channel o)
            const float* fp = f0 + (size_t)o * HWF;
#pragma unroll
            for (int k = 0; k < 8; k++) {
                int q = half * 8 + k;
                r0p[o * R0PITCH + q] = __ldg(fp + hi[q]);
            }
        }
        __syncthreads();

        {   // matvec: 8 points per half-block via 4 packed f32x2 accumulators
            float uo = ush[o];
            unsigned long long a0 = pack_f32x2(uo, uo);
            unsigned long long a1 = a0, a2 = a0, a3 = a0;
#pragma unroll 8
            for (int c = 0; c < CCH; c++) {
                float m = Msh[c * CCH + o];
                unsigned long long m2 = pack_f32x2(m, m);
                const unsigned long long* rp =
                    (const unsigned long long*)&r0p[c * R0PITCH + half * 8];
                unsigned long long r01 = rp[0], r23 = rp[1], r45 = rp[2], r67 = rp[3];
                FMA_F32X2(a0, m2, r01, a0);
                FMA_F32X2(a1, m2, r23, a1);
                FMA_F32X2(a2, m2, r45, a2);
                FMA_F32X2(a3, m2, r67, a3);
            }
            float g[8];
            unpack_f32x2(a0, g[0], g[1]);
            unpack_f32x2(a1, g[2], g[3]);
            unpack_f32x2(a2, g[4], g[5]);
            unpack_f32x2(a3, g[6], g[7]);
            const int s = (o & 31) * 4 + (o >> 5);   // slot for channel o
#pragma unroll
            for (int k = 0; k < 8; k++) {
                int n = n0 + half * 8 + k;
                if (n < N) d_g[(size_t)n * CCH + s] = g[k];
            }
        }
    }
}

// ---------------------------------------------------------------------------
// Kernel 4: one warp per point: correlation (fp16 f1t) + softmax + outputs.
__global__ void __launch_bounds__(256)
corr_kernel(const float* __restrict__ mk0, const float* __restrict__ mk1,
            const int* __restrict__ stride_ptr, float* __restrict__ out, int N)
{
    const int wid = threadIdx.x >> 5, lane = threadIdx.x & 31;
    const int n = blockIdx.x * 8 + wid;
    if (n >= N) return;

    const int stride = stride_ptr ? __ldg(stride_ptr) : 8;
    const int fr = stride >> 1;
    const float scalef = (float)(stride / fr);
    const float halfstr = (float)(stride >> 1);

    const float m0x = __ldg(&mk0[2 * n]), m0y = __ldg(&mk0[2 * n + 1]);
    const float m1x = __ldg(&mk1[2 * n]), m1y = __ldg(&mk1[2 * n + 1]);
    const int cx0 = (int)(m0x * (float)fr), cy0 = (int)(m0y * (float)fr);
    const int cx1 = (int)(m1x * (float)fr), cy1 = (int)(m1y * (float)fr);
    const bool valid = cx0 >= 2 && cx0 + 2 < WF && cy0 >= 2 && cy0 + 2 < HF &&
                       cx1 >= 2 && cx1 + 2 < WF && cy1 >= 2 && cy1 + 2 < HF;
    const int cx1c = min(max(cx1, 2), WF - 3);
    const int cy1c = min(max(cy1, 2), HF - 3);
    const size_t pixb = (size_t)cy1c * WF + cx1c;

    // slots 4*lane..4*lane+3 (d_g written with matching permutation)
    const float4 g4 = *(const float4*)&d_g[(size_t)n * CCH + lane * 4];

    float corr = -FLT_MAX;   // lane p (p<25) ends up holding corr[p]
#pragma unroll
    for (int row = 0; row < 5; row++) {
        const size_t rb = (pixb + (size_t)(row - 2) * WF - 2) * CCH + lane * 4;
        float r[5];
#pragma unroll
        for (int col = 0; col < 5; col++) {
            uint2 u = __ldg((const uint2*)(d_f1t + rb + (size_t)col * CCH));
            __half2 h0 = *reinterpret_cast<__half2*>(&u.x);
            __half2 h1 = *reinterpret_cast<__half2*>(&u.y);
            float2 f01 = __half22float2(h0);
            float2 f23 = __half22float2(h1);
            r[col] = g4.x * f01.x + g4.y * f01.y + g4.z * f23.x + g4.w * f23.y;
        }
#pragma unroll
        for (int d = 16; d; d >>= 1) {
            r[0] += __shfl_xor_sync(0xffffffffu, r[0], d);
            r[1] += __shfl_xor_sync(0xffffffffu, r[1], d);
            r[2] += __shfl_xor_sync(0xffffffffu, r[2], d);
            r[3] += __shfl_xor_sync(0xffffffffu, r[3], d);
            r[4] += __shfl_xor_sync(0xffffffffu, r[4], d);
        }
        const int p0 = row * 5;
#pragma unroll
        for (int col = 0; col < 5; col++)
            if (lane == p0 + col) corr = r[col];
    }

    // softmax over lanes 0..24 + expectation (per-point constant cancels)
    const bool inpatch = lane < 25;
    const int dx = lane % 5 - 2;
    const int dy = lane / 5 - 2;
    float cm = corr;
#pragma unroll
    for (int d = 16; d; d >>= 1)
        cm = fmaxf(cm, __shfl_xor_sync(0xffffffffu, cm, d));
    float e  = inpatch ? __expf(corr - cm) : 0.f;
    float ex = e * (float)dx;
    float ey = e * (float)dy;
    float s  = e;
#pragma unroll
    for (int d = 16; d; d >>= 1) {
        s  += __shfl_xor_sync(0xffffffffu, s,  d);
        ex += __shfl_xor_sync(0xffffffffu, ex, d);
        ey += __shfl_xor_sync(0xffffffffu, ey, d);
    }
    if (lane == 0) {
        out[2 * n]     = m0x * (float)stride + halfstr;
        out[2 * n + 1] = m0y * (float)stride + halfstr;
        const float inv = scalef / s;
        const float ox = valid ? ex * inv : 0.f;
        const float oy = valid ? ey * inv : 0.f;
        out[2 * N + 2 * n]     = m1x * (float)stride + halfstr + ox;
        out[2 * N + 2 * n + 1] = m1y * (float)stride + halfstr + oy;
    }
}

// ---------------------------------------------------------------------------
extern "C" void kernel_launch(void* const* d_in, const int* in_sizes, int n_in,
                              void* d_out, int out_size) {
    const float* mk0 = (const float*)d_in[0];
    const float* mk1 = (const float*)d_in[1];
    const float* f0  = (const float*)d_in[2];
    const float* f1  = (const float*)d_in[3];
    const float* pw  = (const float*)d_in[4];
    const float* pb  = (const float*)d_in[5];
    const int* stridep = (n_in >= 7) ? (const int*)d_in[6] : nullptr;
    float* out = (float*)d_out;

    int N = in_sizes[0] / 2;

    precompute_Mu<<<128, 128>>>(pw, pb);
    transpose_f1<<<HWF / TP_PIX, 256>>>(f1);

    int smbytes = G_SM_FLOATS * 4;
    cudaFuncSetAttribute(g_kernel,
                         cudaFuncAttributeMaxDynamicSharedMemorySize, smbytes);
    int ppb = 48;
    int grid = (N + ppb - 1) / ppb;
    g_kernel<<<grid, 256, smbytes>>>(mk0, f0, stridep, N, ppb);

    corr_kernel<<<(N + 7) / 8, 256>>>(mk0, mk1, stridep, out, N);
}

// round 6
// speedup vs baseline: 2.7880x; 1.0160x over previous
#include <cuda_runtime.h>
#include <cuda_fp16.h>
#include <float.h>
#include <math.h>

#define CCH 128
#define HWF 409600   // 640*640
#define WF 640
#define HF 640

// Precomputed M = W^T W (symmetric) and u = W^T b
__device__ float d_M[CCH * CCH];
__device__ float d_u[CCH];
// Transposed f1 in fp16: [H*W][128 slots]; slot s holds channel c(s) = (s&3)*32 + (s>>2)
__device__ __half d_f1t[(size_t)HWF * CCH];
// g[n] = M * r0[n] + u, stored slot-permuted to match d_f1t
__device__ float d_g[20000 * CCH];

// packed fp32x2 FMA (Blackwell): d = a*b + c elementwise on 2 packed floats
#define FMA_F32X2(d, a, b, c) \
    asm("fma.rn.f32x2 %0, %1, %2, %3;" : "=l"(d) : "l"(a), "l"(b), "l"(c))

__device__ __forceinline__ unsigned long long pack_f32x2(float lo, float hi) {
    unsigned long long r;
    unsigned ulo = __float_as_uint(lo), uhi = __float_as_uint(hi);
    asm("mov.b64 %0, {%1, %2};" : "=l"(r) : "r"(ulo), "r"(uhi));
    return r;
}
__device__ __forceinline__ void unpack_f32x2(unsigned long long v, float& lo, float& hi) {
    unsigned ulo, uhi;
    asm("mov.b64 {%0, %1}, %2;" : "=r"(ulo), "=r"(uhi) : "l"(v));
    lo = __uint_as_float(ulo);
    hi = __uint_as_float(uhi);
}

// ---------------------------------------------------------------------------
// Kernel 1: M = W^T W, u = W^T b. Block o computes row o.
__global__ void precompute_Mu(const float* __restrict__ W, const float* __restrict__ b) {
    __shared__ float wcol[CCH];
    int o = blockIdx.x, t = threadIdx.x;
    wcol[t] = W[t * CCH + o];
    __syncthreads();
    float acc = 0.f;
#pragma unroll 8
    for (int k = 0; k < CCH; k++) acc += wcol[k] * W[k * CCH + t];
    d_M[o * CCH + t] = acc;
    if (t == 0) {
        float uu = 0.f;
        for (int k = 0; k < CCH; k++) uu += wcol[k] * b[k];
        d_u[o] = uu;
    }
}

// ---------------------------------------------------------------------------
// Kernel 2: transpose+convert f1 (C,HW) fp32 -> d_f1t (HW, slots) fp16.
// 64 pixels/block. smem tile fp32 [128 ch][pitch 65] -> column reads conflict-free.
#define TP_PIX 64
__global__ void __launch_bounds__(256) transpose_f1(const float* __restrict__ f1) {
    __shared__ float tile[CCH * 65];
    const int t = threadIdx.x;
    const int pb = blockIdx.x * TP_PIX;
    const int lane = t & 31, wid = t >> 5;

    // Load: 2048 float4 from gmem (coalesced). Scalar STS into pitch-65 tile
    // (float4 STS would be misaligned for odd channels; scalar is safe, ~2-way).
#pragma unroll
    for (int it = 0; it < 8; it++) {
        int idx = it * 256 + t;
        int c = idx >> 4;        // 0..127
        int g = idx & 15;        // float4 group within the 64-pixel row
        float4 v = __ldg((const float4*)(f1 + (size_t)c * HWF + pb + 4 * g));
        float* dst = &tile[c * 65 + 4 * g];
        dst[0] = v.x; dst[1] = v.y; dst[2] = v.z; dst[3] = v.w;
    }
    __syncthreads();

    // Write: one pixel per warp-pass. Lane l reads rows {l, l+32, l+64, l+96},
    // column p: bank = (l + p) % 32 -> conflict-free. Packs slots 4l..4l+3.
#pragma unroll
    for (int pass = 0; pass < 8; pass++) {
        int p = pass * 8 + wid;
        float v0 = tile[(lane      ) * 65 + p];
        float v1 = tile[(lane + 32 ) * 65 + p];
        float v2 = tile[(lane + 64 ) * 65 + p];
        float v3 = tile[(lane + 96 ) * 65 + p];
        __half2 h0 = __floats2half2_rn(v0, v1);
        __half2 h1 = __floats2half2_rn(v2, v3);
        uint2 u;
        u.x = *reinterpret_cast<unsigned*>(&h0);
        u.y = *reinterpret_cast<unsigned*>(&h1);
        *reinterpret_cast<uint2*>(d_f1t + (size_t)(pb + p) * CCH + lane * 4) = u;
    }
}

// ---------------------------------------------------------------------------
// Kernel 3: g[n] = M * r0[n] + u, 16 points per batch, FFMA2 matvec.
// smem floats: Msh[16384] ush[128] r0p[128*20] hi[16 ints]
#define R0PITCH 20   // 80 B rows: 16B-aligned at every half*8 offset
#define G_SM_FLOATS (16384 + 128 + CCH * R0PITCH + 16)
__global__ void __launch_bounds__(256, 3)
g_kernel(const float* __restrict__ mk0, const float* __restrict__ f0,
         const int* __restrict__ stride_ptr, int N, int ptsPerBlock)
{
    extern __shared__ float sm[];
    float* Msh = sm;
    float* ush = sm + 16384;
    float* r0p = sm + 16512;
    int*   hi  = (int*)(sm + 16512 + CCH * R0PITCH);

    const int t = threadIdx.x;
    const int stride = stride_ptr ? __ldg(stride_ptr) : 8;
    const int fr = stride >> 1;

    {   // stage M (float4) and u
        const float4* Ms4 = (const float4*)d_M;
        float4* Md4 = (float4*)Msh;
#pragma unroll
        for (int i = 0; i < 16; i++) Md4[i * 256 + t] = __ldg(&Ms4[i * 256 + t]);
        if (t < CCH) ush[t] = d_u[t];
    }

    const int o    = t & 127;
    const int half = t >> 7;
    const int n0blk = blockIdx.x * ptsPerBlock;

    for (int nb = 0; nb < ptsPerBlock; nb += 16) {
        const int n0 = n0blk + nb;
        if (n0 >= N) break;
        __syncthreads();

        if (t < 16) {
            int n = n0 + t;
            int nc = n < N ? n : N - 1;
            float m0x = mk0[2 * nc], m0y = mk0[2 * nc + 1];
            int cx0 = (int)(m0x * (float)fr), cy0 = (int)(m0y * (float)fr);
            int cx0c = min(max(cx0, 2), WF - 3), cy0c = min(max(cy0, 2), HF - 3);
            hi[t] = cy0c * WF + cx0c;
        }
        __syncthreads();

        {   // gather 8 center values per thread (its half's 8 points, channel o)
            const float* fp = f0 + (size_t)o * HWF;
#pragma unroll
            for (int k = 0; k < 8; k++) {
                int q = half * 8 + k;
                r0p[o * R0PITCH + q] = __ldg(fp + hi[q]);
            }
        }
        __syncthreads();

        {   // matvec: 8 points per half-block via 4 packed f32x2 accumulators
            float uo = ush[o];
            unsigned long long a0 = pack_f32x2(uo, uo);
            unsigned long long a1 = a0, a2 = a0, a3 = a0;
#pragma unroll 8
            for (int c = 0; c < CCH; c++) {
                float m = Msh[c * CCH + o];
                unsigned long long m2 = pack_f32x2(m, m);
                const unsigned long long* rp =
                    (const unsigned long long*)&r0p[c * R0PITCH + half * 8];
                unsigned long long r01 = rp[0], r23 = rp[1], r45 = rp[2], r67 = rp[3];
                FMA_F32X2(a0, m2, r01, a0);
                FMA_F32X2(a1, m2, r23, a1);
                FMA_F32X2(a2, m2, r45, a2);
                FMA_F32X2(a3, m2, r67, a3);
            }
            float g[8];
            unpack_f32x2(a0, g[0], g[1]);
            unpack_f32x2(a1, g[2], g[3]);
            unpack_f32x2(a2, g[4], g[5]);
            unpack_f32x2(a3, g[6], g[7]);
            const int s = (o & 31) * 4 + (o >> 5);   // slot for channel o
#pragma unroll
            for (int k = 0; k < 8; k++) {
                int n = n0 + half * 8 + k;
                if (n < N) d_g[(size_t)n * CCH + s] = g[k];
            }
        }
    }
}

// ---------------------------------------------------------------------------
// Kernel 4: one warp per point: correlation (fp16 f1t) + softmax + outputs.
__global__ void __launch_bounds__(256)
corr_kernel(const float* __restrict__ mk0, const float* __restrict__ mk1,
            const int* __restrict__ stride_ptr, float* __restrict__ out, int N)
{
    const int wid = threadIdx.x >> 5, lane = threadIdx.x & 31;
    const int n = blockIdx.x * 8 + wid;
    if (n >= N) return;

    const int stride = stride_ptr ? __ldg(stride_ptr) : 8;
    const int fr = stride >> 1;
    const float scalef = (float)(stride / fr);
    const float halfstr = (float)(stride >> 1);

    const float m0x = __ldg(&mk0[2 * n]), m0y = __ldg(&mk0[2 * n + 1]);
    const float m1x = __ldg(&mk1[2 * n]), m1y = __ldg(&mk1[2 * n + 1]);
    const int cx0 = (int)(m0x * (float)fr), cy0 = (int)(m0y * (float)fr);
    const int cx1 = (int)(m1x * (float)fr), cy1 = (int)(m1y * (float)fr);
    const bool valid = cx0 >= 2 && cx0 + 2 < WF && cy0 >= 2 && cy0 + 2 < HF &&
                       cx1 >= 2 && cx1 + 2 < WF && cy1 >= 2 && cy1 + 2 < HF;
    const int cx1c = min(max(cx1, 2), WF - 3);
    const int cy1c = min(max(cy1, 2), HF - 3);
    const size_t pixb = (size_t)cy1c * WF + cx1c;

    // slots 4*lane..4*lane+3 (d_g written with matching permutation)
    const float4 g4 = *(const float4*)&d_g[(size_t)n * CCH + lane * 4];

    float corr = -FLT_MAX;   // lane p (p<25) ends up holding corr[p]
#pragma unroll
    for (int row = 0; row < 5; row++) {
        const size_t rb = (pixb + (size_t)(row - 2) * WF - 2) * CCH + lane * 4;
        float r[5];
#pragma unroll
        for (int col = 0; col < 5; col++) {
            uint2 u = __ldg((const uint2*)(d_f1t + rb + (size_t)col * CCH));
            __half2 h0 = *reinterpret_cast<__half2*>(&u.x);
            __half2 h1 = *reinterpret_cast<__half2*>(&u.y);
            float2 f01 = __half22float2(h0);
            float2 f23 = __half22float2(h1);
            r[col] = g4.x * f01.x + g4.y * f01.y + g4.z * f23.x + g4.w * f23.y;
        }
#pragma unroll
        for (int d = 16; d; d >>= 1) {
            r[0] += __shfl_xor_sync(0xffffffffu, r[0], d);
            r[1] += __shfl_xor_sync(0xffffffffu, r[1], d);
            r[2] += __shfl_xor_sync(0xffffffffu, r[2], d);
            r[3] += __shfl_xor_sync(0xffffffffu, r[3], d);
            r[4] += __shfl_xor_sync(0xffffffffu, r[4], d);
        }
        const int p0 = row * 5;
#pragma unroll
        for (int col = 0; col < 5; col++)
            if (lane == p0 + col) corr = r[col];
    }

    // softmax over lanes 0..24 + expectation (per-point constant cancels)
    const bool inpatch = lane < 25;
    const int dx = lane % 5 - 2;
    const int dy = lane / 5 - 2;
    float cm = corr;
#pragma unroll
    for (int d = 16; d; d >>= 1)
        cm = fmaxf(cm, __shfl_xor_sync(0xffffffffu, cm, d));
    float e  = inpatch ? __expf(corr - cm) : 0.f;
    float ex = e * (float)dx;
    float ey = e * (float)dy;
    float s  = e;
#pragma unroll
    for (int d = 16; d; d >>= 1) {
        s  += __shfl_xor_sync(0xffffffffu, s,  d);
        ex += __shfl_xor_sync(0xffffffffu, ex, d);
        ey += __shfl_xor_sync(0xffffffffu, ey, d);
    }
    if (lane == 0) {
        out[2 * n]     = m0x * (float)stride + halfstr;
        out[2 * n + 1] = m0y * (float)stride + halfstr;
        const float inv = scalef / s;
        const float ox = valid ? ex * inv : 0.f;
        const float oy = valid ? ey * inv : 0.f;
        out[2 * N + 2 * n]     = m1x * (float)stride + halfstr + ox;
        out[2 * N + 2 * n + 1] = m1y * (float)stride + halfstr + oy;
    }
}

// ---------------------------------------------------------------------------
extern "C" void kernel_launch(void* const* d_in, const int* in_sizes, int n_in,
                              void* d_out, int out_size) {
    const float* mk0 = (const float*)d_in[0];
    const float* mk1 = (const float*)d_in[1];
    const float* f0  = (const float*)d_in[2];
    const float* f1  = (const float*)d_in[3];
    const float* pw  = (const float*)d_in[4];
    const float* pb  = (const float*)d_in[5];
    const int* stridep = (n_in >= 7) ? (const int*)d_in[6] : nullptr;
    float* out = (float*)d_out;

    int N = in_sizes[0] / 2;

    precompute_Mu<<<128, 128>>>(pw, pb);
    transpose_f1<<<HWF / TP_PIX, 256>>>(f1);

    int smbytes = G_SM_FLOATS * 4;
    cudaFuncSetAttribute(g_kernel,
                         cudaFuncAttributeMaxDynamicSharedMemorySize, smbytes);
    int ppb = 48;
    int grid = (N + ppb - 1) / ppb;
    g_kernel<<<grid, 256, smbytes>>>(mk0, f0, stridep, N, ppb);

    corr_kernel<<<(N + 7) / 8, 256>>>(mk0, mk1, stridep, out, N);
}